// round 14
// baseline (speedup 1.0000x reference)
#include <cuda_runtime.h>
#include <cuda_bf16.h>
#include <cstdint>

#define BB 16
#define NL 64
#define NP 512

// Output layout in d_out (float32, reference return order)
#define PI_OFF   0LL
#define SG_OFF   5242880LL          // M*10
#define MU_OFF   10485760LL
#define D_OFF    15728640LL
#define MK_OFF   16252928LL

// Pre-packed weight fragments (lane-major) + bias, built once per launch
__device__ __align__(16) unsigned g_wf[8 * 16 * 32];  // [ks][which][lane]
__device__ __align__(16) float    g_bs[32];

// smem (u32 offsets): atoms 9216 u32 (36864B), wf 4096, bias 32
// Epilogue staging ob[3][256][10] = 7680 f32 (30720B) aliases atoms.
#define AT_U     0
#define WF_U     9216
#define BS_U     13312
#define OB_U     0
#define SMEM_U   13344
#define SMEM_BYTES (SMEM_U*4)       // 53376 B

// m16n8k16 bf16 MMA, fp32 accumulate
#define MMA(D, A, B0, B1) \
  asm volatile("mma.sync.aligned.m16n8k16.row.col.f32.bf16.bf16.f32 " \
      "{%0,%1,%2,%3}, {%4,%5,%6,%7}, {%8,%9}, {%0,%1,%2,%3};" \
      : "+f"((D)[0]), "+f"((D)[1]), "+f"((D)[2]), "+f"((D)[3]) \
      : "r"((A)[0]), "r"((A)[1]), "r"((A)[2]), "r"((A)[3]), "r"(B0), "r"(B1))

__device__ __forceinline__ void split4(float4 v, uint2& hv, uint2& lv) {
    __nv_bfloat162 h0 = __floats2bfloat162_rn(v.x, v.y);
    __nv_bfloat162 h1 = __floats2bfloat162_rn(v.z, v.w);
    float2 f0 = __bfloat1622float2(h0);
    float2 f1 = __bfloat1622float2(h1);
    __nv_bfloat162 l0 = __floats2bfloat162_rn(v.x - f0.x, v.y - f0.y);
    __nv_bfloat162 l1 = __floats2bfloat162_rn(v.z - f1.x, v.w - f1.y);
    hv = make_uint2(*(unsigned*)&h0, *(unsigned*)&h1);
    lv = make_uint2(*(unsigned*)&l0, *(unsigned*)&l1);
}

__device__ __forceinline__ void cp_async16(void* dst_smem, const void* src) {
    unsigned d = (unsigned)__cvta_generic_to_shared(dst_smem);
    asm volatile("cp.async.cg.shared.global [%0], [%1], 16;\n" :: "r"(d), "l"(src));
}
#define CP_COMMIT() asm volatile("cp.async.commit_group;\n")
#define CP_WAIT0()  asm volatile("cp.async.wait_group 0;\n")

// ---------------------------------------------------------------------------
// One-shot W fragment pack (identical to round 13)
// ---------------------------------------------------------------------------
__global__ void pack_wf(const float* __restrict__ Wpi, const float* __restrict__ bpi,
                        const float* __restrict__ Wsig, const float* __restrict__ bsig,
                        const float* __restrict__ Wmu, const float* __restrict__ bmu)
{
    int idx = blockIdx.x * 256 + threadIdx.x;    // 0..4095
    int ksw  = idx >> 9;
    int which = (idx >> 5) & 15;
    int ln   = idx & 31;
    int n    = which & 3, type = which >> 2;
    int qd_  = ln & 3,  g4_ = ln >> 2;
    int col  = 8*n + g4_;
    int kp   = 8*ksw + 2*qd_ + (type & 1);       // k rows 2kp, 2kp+1
    float w0 = 0.f, w1 = 0.f;
    if (col < 10)      { w0 = Wpi [kp*20 + col];      w1 = Wpi [kp*20 + 10 + col]; }
    else if (col < 20) { w0 = Wsig[kp*20 + col - 10]; w1 = Wsig[kp*20 + col]; }
    else if (col < 30) { w0 = Wmu [kp*20 + col - 20]; w1 = Wmu [kp*20 + col - 10]; }
    __nv_bfloat162 hh = __floats2bfloat162_rn(w0, w1);
    if (type >= 2) {
        float2 hf = __bfloat1622float2(hh);
        hh = __floats2bfloat162_rn(w0 - hf.x, w1 - hf.y);
    }
    g_wf[idx] = *(unsigned*)&hh;
    if (idx < 32) {
        float bv = 0.f;
        if (idx < 10) bv = bpi[idx];
        else if (idx < 20) bv = bsig[idx - 10];
        else if (idx < 30) bv = bmu[idx - 20];
        g_bs[idx] = bv;
    }
}

__global__ __launch_bounds__(256, 2)
void fused_kernel(const float* __restrict__ pos_l, const float* __restrict__ pos_p,
                  const float* __restrict__ X, const int* __restrict__ mask,
                  float* __restrict__ out)
{
    extern __shared__ unsigned smU[];
    float4*   sm4 = (float4*)(smU + AT_U);       // atom staging
    unsigned* wf  = smU + WF_U;
    float*    bs  = (float*)(smU + BS_U);
    float*    ob  = (float*)(smU + OB_U);        // aliases atoms (post-GEMM)

    const int tid  = threadIdx.x;
    const int lane = tid & 31, w = tid >> 5;
    const int qd   = lane & 3, g4 = lane >> 2;
    const int blk  = blockIdx.x;                 // 2048: b(4b) | i2(5b) | jq(2b)
    const int b    = blk >> 7;
    const int i0   = 2 * ((blk >> 2) & 31);
    const int jofs = (blk & 3) * 128;
    const long long m0a = ((long long)(b*NL + i0))*NP + jofs;   // i0 block
    const long long m0b = m0a + NP;                              // i0+1 block
    const float4* Xg4 = (const float4*)X;

    // ---- stage atoms + W fragments + bias, all coalesced cp.async ----
    {
        const float4* ag4 = (const float4*)(pos_p + ((long long)b*NP + jofs)*72);
        #pragma unroll
        for (int u = 0; u < 9; u++)
            cp_async16(sm4 + u*256 + tid, ag4 + u*256 + tid);
        #pragma unroll
        for (int u = 0; u < 4; u++)
            cp_async16((float4*)wf + u*256 + tid, (const float4*)g_wf + u*256 + tid);
        if (tid < 8)
            cp_async16((float4*)bs + tid, (const float4*)g_bs + tid);
        CP_COMMIT();
    }

    // warp row base: warps 0-3 -> i0 block, warps 4-7 -> i0+1 block
    const long long mw = (w < 4) ? (m0a + 32*w) : (m0b + 32*(w - 4));

    // ---- GEMM chunk 0 into registers (in flight during dist) ----
    const float4* Xr = Xg4 + (mw + g4)*32 + qd;
    float4 buf[2][8];
    #define LOADP(pp, B) { \
        _Pragma("unroll") \
        for (int u2 = 0; u2 < 8; u2++) { \
            int s2_ = u2 >> 2, mt_ = (u2 >> 1) & 1, r_ = u2 & 1; \
            (B)[u2] = Xr[(16*mt_ + 8*r_)*32 + 4*(2*(pp) + s2_)]; \
        } }
    LOADP(0, buf[0]);

    // ---- one barrier: atoms + wf + bs staged and visible ----
    CP_WAIT0();
    __syncthreads();

    // ---- min-distance: 2 threads per j, 12 atoms each, BOTH i values ----
    {
        const float* p0 = pos_l + (long long)(b*NL + i0)*3;
        float qx0 = p0[0], qy0 = p0[1], qz0 = p0[2];
        float qw0 = qx0*qx0 + qy0*qy0 + qz0*qz0;
        float qx1 = p0[3], qy1 = p0[4], qz1 = p0[5];
        float qw1 = qx1*qx1 + qy1*qy1 + qz1*qz1;
        const int jloc = tid >> 1, half = tid & 1;
        const float4* As = sm4 + jloc*18 + half*9;
        float m2a = 1e30f, m2b = 1e30f;
        #pragma unroll
        for (int u = 0; u < 3; u++) {            // 3 x (3 float4 = 4 atoms)
            float4 v0 = As[u*3], v1 = As[u*3+1], v2 = As[u*3+2];
            float c[12] = {v0.x,v0.y,v0.z,v0.w, v1.x,v1.y,v1.z,v1.w,
                           v2.x,v2.y,v2.z,v2.w};
            #pragma unroll
            for (int a = 0; a < 4; a++) {
                float ax = c[a*3], ay = c[a*3+1], az = c[a*3+2];
                float aw = ax*ax + ay*ay + az*az;
                float d2a = (qw0 + aw) - 2.f*(ax*qx0 + ay*qy0 + az*qz0);
                d2a = (d2a < 0.f) ? 1e30f : d2a;  // sqrt(neg)=NaN -> 10000
                m2a = fminf(m2a, d2a);
                float d2b = (qw1 + aw) - 2.f*(ax*qx1 + ay*qy1 + az*qz1);
                d2b = (d2b < 0.f) ? 1e30f : d2b;
                m2b = fminf(m2b, d2b);
            }
        }
        m2a = fminf(m2a, __shfl_xor_sync(0xffffffffu, m2a, 1));
        m2b = fminf(m2b, __shfl_xor_sync(0xffffffffu, m2b, 1));
        if (half == 0) {
            long long ma = m0a + jloc, mb = m0b + jloc;
            float da = (m2a > 9e29f) ? 10000.f : sqrtf(m2a);
            bool mka = (mask[ma] != 0);
            out[D_OFF + ma]  = mka ? da : 0.f;
            out[MK_OFF + ma] = mka ? 1.f : 0.f;
            float db = (m2b > 9e29f) ? 10000.f : sqrtf(m2b);
            bool mkb = (mask[mb] != 0);
            out[D_OFF + mb]  = mkb ? db : 0.f;
            out[MK_OFF + mb] = mkb ? 1.f : 0.f;
        }
    }

    // ---- GEMM [256,128]x[128,32]: warp = 32 rows (mt=2), W amortized ----
    float acc[2][4][4];
    #pragma unroll
    for (int mt = 0; mt < 2; mt++)
        #pragma unroll
        for (int n = 0; n < 4; n++) {
            float c0 = bs[8*n + 2*qd], c1 = bs[8*n + 2*qd + 1];
            acc[mt][n][0] = c0; acc[mt][n][1] = c1;
            acc[mt][n][2] = c0; acc[mt][n][3] = c1;
        }

    #pragma unroll
    for (int p = 0; p < 4; p++) {
        if (p < 3) LOADP(p + 1, buf[(p + 1) & 1]);
        #pragma unroll
        for (int s2 = 0; s2 < 2; s2++) {
            int ks = 2*p + s2;
            const unsigned* wfs = wf + ks*512 + lane;   // conflict-free LDS.32
            unsigned bw[16];
            #pragma unroll
            for (int q = 0; q < 16; q++) bw[q] = wfs[q*32];
            #pragma unroll
            for (int mt = 0; mt < 2; mt++) {
                float4 x0 = buf[p & 1][s2*4 + 2*mt];
                float4 x1 = buf[p & 1][s2*4 + 2*mt + 1];
                uint2 h0, l0, h1, l1;
                split4(x0, h0, l0); split4(x1, h1, l1);
                unsigned ah[4] = {h0.x, h1.x, h0.y, h1.y};
                unsigned al[4] = {l0.x, l1.x, l0.y, l1.y};
                #pragma unroll
                for (int n = 0; n < 4; n++) {
                    MMA(acc[mt][n], ah, bw[n],     bw[4 + n]);    // hi*Whi
                    MMA(acc[mt][n], al, bw[n],     bw[4 + n]);    // lo*Whi
                    MMA(acc[mt][n], ah, bw[8 + n], bw[12 + n]);   // hi*Wlo
                }
            }
        }
    }
    __syncthreads();           // dist smem reads done before ob aliases atoms

    // ---- epilogue in fragment layout, stage to smem [3][256][10] ----
    #pragma unroll
    for (int mt = 0; mt < 2; mt++) {
        int rbase = 32*w + 16*mt + g4;   // logical row 0..255
        #pragma unroll
        for (int h = 0; h < 2; h++) {
            int r = rbase + 8*h;
            float v0[4], v1[4];
            #pragma unroll
            for (int n = 0; n < 4; n++) {
                v0[n] = acc[mt][n][2*h];
                v1[n] = acc[mt][n][2*h + 1];
            }
            // pi = softmax over cols 0..9 (quad reduce)
            float mx = fmaxf(v0[0], v1[0]);
            if (qd == 0) mx = fmaxf(mx, fmaxf(v0[1], v1[1]));
            mx = fmaxf(mx, __shfl_xor_sync(0xffffffffu, mx, 1));
            mx = fmaxf(mx, __shfl_xor_sync(0xffffffffu, mx, 2));
            float e0 = __expf(v0[0] - mx), e1 = __expf(v1[0] - mx);
            float e8 = 0.f, e9 = 0.f;
            float ssum = e0 + e1;
            if (qd == 0) { e8 = __expf(v0[1] - mx); e9 = __expf(v1[1] - mx); ssum += e8 + e9; }
            ssum += __shfl_xor_sync(0xffffffffu, ssum, 1);
            ssum += __shfl_xor_sync(0xffffffffu, ssum, 2);
            float inv = __fdividef(1.f, ssum);
            float* prow = ob + r*10;
            *(float2*)(prow + 2*qd) = make_float2(e0*inv, e1*inv);
            if (qd == 0) *(float2*)(prow + 8) = make_float2(e8*inv, e9*inv);
            // sigma cols 10..19
            float* srow = ob + 2560 + r*10;
            if (qd >= 1) {
                float a0 = v0[1], a1 = v1[1];
                float l0 = (a0 > 0.f) ? a0 : 0.01f*a0;
                float l1 = (a1 > 0.f) ? a1 : 0.01f*a1;
                *(float2*)(srow + 2*qd - 2) =
                    make_float2(fmaxf(l0 + 1.1f, 1e-6f), fmaxf(l1 + 1.1f, 1e-6f));
            }
            if (qd <= 1) {
                float a0 = v0[2], a1 = v1[2];
                float l0 = (a0 > 0.f) ? a0 : 0.01f*a0;
                float l1 = (a1 > 0.f) ? a1 : 0.01f*a1;
                *(float2*)(srow + 6 + 2*qd) =
                    make_float2(fmaxf(l0 + 1.1f, 1e-6f), fmaxf(l1 + 1.1f, 1e-6f));
            }
            // mu cols 20..29
            float* mrow = ob + 5120 + r*10;
            if (qd >= 2) {
                float a0 = v0[2], a1 = v1[2];
                float l0 = (a0 > 0.f) ? a0 : 0.01f*a0;
                float l1 = (a1 > 0.f) ? a1 : 0.01f*a1;
                *(float2*)(mrow + 2*qd - 4) = make_float2(l0 + 1.f, l1 + 1.f);
            }
            if (qd <= 2) {
                float a0 = v0[3], a1 = v1[3];
                float l0 = (a0 > 0.f) ? a0 : 0.01f*a0;
                float l1 = (a1 > 0.f) ? a1 : 0.01f*a1;
                *(float2*)(mrow + 4 + 2*qd) = make_float2(l0 + 1.f, l1 + 1.f);
            }
        }
    }
    __syncthreads();

    // ---- coalesced float4 store: 3 outputs x 2 blocks x 320 float4 ----
    const float4* obv = (const float4*)ob;
    #pragma unroll
    for (int it = 0; it < 8; it++) {
        int idx = it*256 + tid;
        if (idx < 1920) {
            int type = idx / 640;
            int rem  = idx % 640;
            int hblk = rem / 320;
            int wi   = rem % 320;
            long long mb = hblk ? m0b : m0a;
            long long goff = (type == 0 ? PI_OFF : type == 1 ? SG_OFF : MU_OFF) + mb*10;
            *((float4*)(out + goff) + wi) = obv[idx];
        }
    }
}

extern "C" void kernel_launch(void* const* d_in, const int* in_sizes, int n_in,
                              void* d_out, int out_size) {
    const float* pos_l    = (const float*)d_in[0];
    const float* pos_p    = (const float*)d_in[1];
    const float* Interact = (const float*)d_in[2];
    const int*   mask     = (const int*)d_in[3];
    const float* W_pi     = (const float*)d_in[4];
    const float* b_pi     = (const float*)d_in[5];
    const float* W_sigma  = (const float*)d_in[6];
    const float* b_sigma  = (const float*)d_in[7];
    const float* W_mu     = (const float*)d_in[8];
    const float* b_mu     = (const float*)d_in[9];
    float* out = (float*)d_out;

    pack_wf<<<16, 256>>>(W_pi, b_pi, W_sigma, b_sigma, W_mu, b_mu);

    cudaFuncSetAttribute(fused_kernel, cudaFuncAttributeMaxDynamicSharedMemorySize,
                         SMEM_BYTES);
    fused_kernel<<<BB * (NL/2) * 4, 256, SMEM_BYTES>>>(pos_l, pos_p, Interact,
                                                       mask, out);
}

// round 15
// speedup vs baseline: 1.0032x; 1.0032x over previous
#include <cuda_runtime.h>
#include <cuda_bf16.h>
#include <cstdint>

#define BB 16
#define NL 64
#define NP 512

// Output layout in d_out (float32, reference return order)
#define PI_OFF   0LL
#define SG_OFF   5242880LL          // M*10
#define MU_OFF   10485760LL
#define D_OFF    15728640LL
#define MK_OFF   16252928LL

// Pre-packed weight fragments (lane-major) + bias, built once per launch
__device__ __align__(16) unsigned g_wf[8 * 16 * 32];  // [ks][which][lane]
__device__ __align__(16) float    g_bs[32];

// smem (u32 offsets): atoms 9216 u32 (36864B), wf 4096, bias 32
// Epilogue staging ob[3][256][10] = 7680 f32 (30720B) aliases atoms.
#define AT_U     0
#define WF_U     9216
#define BS_U     13312
#define OB_U     0
#define SMEM_U   13344
#define SMEM_BYTES (SMEM_U*4)       // 53376 B -> 3 CTAs/SM

// m16n8k16 bf16 MMA, fp32 accumulate
#define MMA(D, A, B0, B1) \
  asm volatile("mma.sync.aligned.m16n8k16.row.col.f32.bf16.bf16.f32 " \
      "{%0,%1,%2,%3}, {%4,%5,%6,%7}, {%8,%9}, {%0,%1,%2,%3};" \
      : "+f"((D)[0]), "+f"((D)[1]), "+f"((D)[2]), "+f"((D)[3]) \
      : "r"((A)[0]), "r"((A)[1]), "r"((A)[2]), "r"((A)[3]), "r"(B0), "r"(B1))

__device__ __forceinline__ void split4(float4 v, uint2& hv, uint2& lv) {
    __nv_bfloat162 h0 = __floats2bfloat162_rn(v.x, v.y);
    __nv_bfloat162 h1 = __floats2bfloat162_rn(v.z, v.w);
    float2 f0 = __bfloat1622float2(h0);
    float2 f1 = __bfloat1622float2(h1);
    __nv_bfloat162 l0 = __floats2bfloat162_rn(v.x - f0.x, v.y - f0.y);
    __nv_bfloat162 l1 = __floats2bfloat162_rn(v.z - f1.x, v.w - f1.y);
    hv = make_uint2(*(unsigned*)&h0, *(unsigned*)&h1);
    lv = make_uint2(*(unsigned*)&l0, *(unsigned*)&l1);
}

__device__ __forceinline__ void cp_async16(void* dst_smem, const void* src) {
    unsigned d = (unsigned)__cvta_generic_to_shared(dst_smem);
    asm volatile("cp.async.cg.shared.global [%0], [%1], 16;\n" :: "r"(d), "l"(src));
}
#define CP_COMMIT() asm volatile("cp.async.commit_group;\n")
#define CP_WAIT0()  asm volatile("cp.async.wait_group 0;\n")

// ---------------------------------------------------------------------------
// One-shot W fragment pack (identical to rounds 13/14)
// ---------------------------------------------------------------------------
__global__ void pack_wf(const float* __restrict__ Wpi, const float* __restrict__ bpi,
                        const float* __restrict__ Wsig, const float* __restrict__ bsig,
                        const float* __restrict__ Wmu, const float* __restrict__ bmu)
{
    int idx = blockIdx.x * 256 + threadIdx.x;    // 0..4095
    int ksw  = idx >> 9;
    int which = (idx >> 5) & 15;
    int ln   = idx & 31;
    int n    = which & 3, type = which >> 2;
    int qd_  = ln & 3,  g4_ = ln >> 2;
    int col  = 8*n + g4_;
    int kp   = 8*ksw + 2*qd_ + (type & 1);       // k rows 2kp, 2kp+1
    float w0 = 0.f, w1 = 0.f;
    if (col < 10)      { w0 = Wpi [kp*20 + col];      w1 = Wpi [kp*20 + 10 + col]; }
    else if (col < 20) { w0 = Wsig[kp*20 + col - 10]; w1 = Wsig[kp*20 + col]; }
    else if (col < 30) { w0 = Wmu [kp*20 + col - 20]; w1 = Wmu [kp*20 + col - 10]; }
    __nv_bfloat162 hh = __floats2bfloat162_rn(w0, w1);
    if (type >= 2) {
        float2 hf = __bfloat1622float2(hh);
        hh = __floats2bfloat162_rn(w0 - hf.x, w1 - hf.y);
    }
    g_wf[idx] = *(unsigned*)&hh;
    if (idx < 32) {
        float bv = 0.f;
        if (idx < 10) bv = bpi[idx];
        else if (idx < 20) bv = bsig[idx - 10];
        else if (idx < 30) bv = bmu[idx - 20];
        g_bs[idx] = bv;
    }
}

__global__ __launch_bounds__(256, 3)
void fused_kernel(const float* __restrict__ pos_l, const float* __restrict__ pos_p,
                  const float* __restrict__ X, const int* __restrict__ mask,
                  float* __restrict__ out)
{
    extern __shared__ unsigned smU[];
    float4*   sm4 = (float4*)(smU + AT_U);       // atom staging
    unsigned* wf  = smU + WF_U;
    float*    bs  = (float*)(smU + BS_U);
    float*    ob  = (float*)(smU + OB_U);        // aliases atoms (post-GEMM)

    const int tid  = threadIdx.x;
    const int lane = tid & 31, w = tid >> 5;
    const int qd   = lane & 3, g4 = lane >> 2;
    const int blk  = blockIdx.x;                 // 2048: b(4b) | i2(5b) | jq(2b)
    const int b    = blk >> 7;
    const int i0   = 2 * ((blk >> 2) & 31);
    const int jofs = (blk & 3) * 128;
    const long long m0a = ((long long)(b*NL + i0))*NP + jofs;   // i0 block
    const long long m0b = m0a + NP;                              // i0+1 block
    const float4* Xg4 = (const float4*)X;

    // ---- stage atoms + W fragments + bias, all coalesced cp.async ----
    {
        const float4* ag4 = (const float4*)(pos_p + ((long long)b*NP + jofs)*72);
        #pragma unroll
        for (int u = 0; u < 9; u++)
            cp_async16(sm4 + u*256 + tid, ag4 + u*256 + tid);
        #pragma unroll
        for (int u = 0; u < 4; u++)
            cp_async16((float4*)wf + u*256 + tid, (const float4*)g_wf + u*256 + tid);
        if (tid < 8)
            cp_async16((float4*)bs + tid, (const float4*)g_bs + tid);
        CP_COMMIT();
    }

    // warp row base: warps 0-3 -> i0 block, warps 4-7 -> i0+1 block
    const long long mw = (w < 4) ? (m0a + 32*w) : (m0b + 32*(w - 4));
    const float4* Xr = Xg4 + (mw + g4)*32 + qd;

    // ---- one barrier: atoms + wf + bs staged and visible ----
    CP_WAIT0();
    __syncthreads();

    // ---- min-distance: 2 threads per j, 12 atoms each, BOTH i values ----
    {
        const float* p0 = pos_l + (long long)(b*NL + i0)*3;
        float qx0 = p0[0], qy0 = p0[1], qz0 = p0[2];
        float qw0 = qx0*qx0 + qy0*qy0 + qz0*qz0;
        float qx1 = p0[3], qy1 = p0[4], qz1 = p0[5];
        float qw1 = qx1*qx1 + qy1*qy1 + qz1*qz1;
        const int jloc = tid >> 1, half = tid & 1;
        const float4* As = sm4 + jloc*18 + half*9;
        float m2a = 1e30f, m2b = 1e30f;
        #pragma unroll
        for (int u = 0; u < 3; u++) {            // 3 x (3 float4 = 4 atoms)
            float4 v0 = As[u*3], v1 = As[u*3+1], v2 = As[u*3+2];
            float c[12] = {v0.x,v0.y,v0.z,v0.w, v1.x,v1.y,v1.z,v1.w,
                           v2.x,v2.y,v2.z,v2.w};
            #pragma unroll
            for (int a = 0; a < 4; a++) {
                float ax = c[a*3], ay = c[a*3+1], az = c[a*3+2];
                float aw = ax*ax + ay*ay + az*az;
                float d2a = (qw0 + aw) - 2.f*(ax*qx0 + ay*qy0 + az*qz0);
                d2a = (d2a < 0.f) ? 1e30f : d2a;  // sqrt(neg)=NaN -> 10000
                m2a = fminf(m2a, d2a);
                float d2b = (qw1 + aw) - 2.f*(ax*qx1 + ay*qy1 + az*qz1);
                d2b = (d2b < 0.f) ? 1e30f : d2b;
                m2b = fminf(m2b, d2b);
            }
        }
        m2a = fminf(m2a, __shfl_xor_sync(0xffffffffu, m2a, 1));
        m2b = fminf(m2b, __shfl_xor_sync(0xffffffffu, m2b, 1));
        if (half == 0) {
            long long ma = m0a + jloc, mb = m0b + jloc;
            float da = (m2a > 9e29f) ? 10000.f : sqrtf(m2a);
            bool mka = (mask[ma] != 0);
            out[D_OFF + ma]  = mka ? da : 0.f;
            out[MK_OFF + ma] = mka ? 1.f : 0.f;
            float db = (m2b > 9e29f) ? 10000.f : sqrtf(m2b);
            bool mkb = (mask[mb] != 0);
            out[D_OFF + mb]  = mkb ? db : 0.f;
            out[MK_OFF + mb] = mkb ? 1.f : 0.f;
        }
    }

    // ---- GEMM [256,128]x[128,32]: warp = 32 rows (mt=2), ks-granular X ----
    float acc[2][4][4];
    #pragma unroll
    for (int mt = 0; mt < 2; mt++)
        #pragma unroll
        for (int n = 0; n < 4; n++) {
            float c0 = bs[8*n + 2*qd], c1 = bs[8*n + 2*qd + 1];
            acc[mt][n][0] = c0; acc[mt][n][1] = c1;
            acc[mt][n][2] = c0; acc[mt][n][3] = c1;
        }

    #pragma unroll 1
    for (int ks = 0; ks < 8; ks++) {
        // X for this k16-step: physical f4col = 4*ks + qd (k-permuted)
        float4 xb[4];
        #pragma unroll
        for (int u2 = 0; u2 < 4; u2++) {
            int mt_ = u2 >> 1, r_ = u2 & 1;
            xb[u2] = Xr[(16*mt_ + 8*r_)*32 + 4*ks];
        }
        const unsigned* wfs = wf + ks*512 + lane;   // conflict-free LDS.32
        unsigned bw[16];
        #pragma unroll
        for (int q = 0; q < 16; q++) bw[q] = wfs[q*32];
        #pragma unroll
        for (int mt = 0; mt < 2; mt++) {
            uint2 h0, l0, h1, l1;
            split4(xb[2*mt],     h0, l0);
            split4(xb[2*mt + 1], h1, l1);
            unsigned ah[4] = {h0.x, h1.x, h0.y, h1.y};
            unsigned al[4] = {l0.x, l1.x, l0.y, l1.y};
            #pragma unroll
            for (int n = 0; n < 4; n++) {
                MMA(acc[mt][n], ah, bw[n],     bw[4 + n]);    // hi*Whi
                MMA(acc[mt][n], al, bw[n],     bw[4 + n]);    // lo*Whi
                MMA(acc[mt][n], ah, bw[8 + n], bw[12 + n]);   // hi*Wlo
            }
        }
    }
    __syncthreads();           // dist smem reads done before ob aliases atoms

    // ---- epilogue in fragment layout, stage to smem [3][256][10] ----
    #pragma unroll
    for (int mt = 0; mt < 2; mt++) {
        int rbase = 32*w + 16*mt + g4;   // logical row 0..255
        #pragma unroll
        for (int h = 0; h < 2; h++) {
            int r = rbase + 8*h;
            float v0[4], v1[4];
            #pragma unroll
            for (int n = 0; n < 4; n++) {
                v0[n] = acc[mt][n][2*h];
                v1[n] = acc[mt][n][2*h + 1];
            }
            // pi = softmax over cols 0..9 (quad reduce)
            float mx = fmaxf(v0[0], v1[0]);
            if (qd == 0) mx = fmaxf(mx, fmaxf(v0[1], v1[1]));
            mx = fmaxf(mx, __shfl_xor_sync(0xffffffffu, mx, 1));
            mx = fmaxf(mx, __shfl_xor_sync(0xffffffffu, mx, 2));
            float e0 = __expf(v0[0] - mx), e1 = __expf(v1[0] - mx);
            float e8 = 0.f, e9 = 0.f;
            float ssum = e0 + e1;
            if (qd == 0) { e8 = __expf(v0[1] - mx); e9 = __expf(v1[1] - mx); ssum += e8 + e9; }
            ssum += __shfl_xor_sync(0xffffffffu, ssum, 1);
            ssum += __shfl_xor_sync(0xffffffffu, ssum, 2);
            float inv = __fdividef(1.f, ssum);
            float* prow = ob + r*10;
            *(float2*)(prow + 2*qd) = make_float2(e0*inv, e1*inv);
            if (qd == 0) *(float2*)(prow + 8) = make_float2(e8*inv, e9*inv);
            // sigma cols 10..19
            float* srow = ob + 2560 + r*10;
            if (qd >= 1) {
                float a0 = v0[1], a1 = v1[1];
                float l0 = (a0 > 0.f) ? a0 : 0.01f*a0;
                float l1 = (a1 > 0.f) ? a1 : 0.01f*a1;
                *(float2*)(srow + 2*qd - 2) =
                    make_float2(fmaxf(l0 + 1.1f, 1e-6f), fmaxf(l1 + 1.1f, 1e-6f));
            }
            if (qd <= 1) {
                float a0 = v0[2], a1 = v1[2];
                float l0 = (a0 > 0.f) ? a0 : 0.01f*a0;
                float l1 = (a1 > 0.f) ? a1 : 0.01f*a1;
                *(float2*)(srow + 6 + 2*qd) =
                    make_float2(fmaxf(l0 + 1.1f, 1e-6f), fmaxf(l1 + 1.1f, 1e-6f));
            }
            // mu cols 20..29
            float* mrow = ob + 5120 + r*10;
            if (qd >= 2) {
                float a0 = v0[2], a1 = v1[2];
                float l0 = (a0 > 0.f) ? a0 : 0.01f*a0;
                float l1 = (a1 > 0.f) ? a1 : 0.01f*a1;
                *(float2*)(mrow + 2*qd - 4) = make_float2(l0 + 1.f, l1 + 1.f);
            }
            if (qd <= 2) {
                float a0 = v0[3], a1 = v1[3];
                float l0 = (a0 > 0.f) ? a0 : 0.01f*a0;
                float l1 = (a1 > 0.f) ? a1 : 0.01f*a1;
                *(float2*)(mrow + 4 + 2*qd) = make_float2(l0 + 1.f, l1 + 1.f);
            }
        }
    }
    __syncthreads();

    // ---- coalesced float4 store: 3 outputs x 2 blocks x 320 float4 ----
    const float4* obv = (const float4*)ob;
    #pragma unroll
    for (int it = 0; it < 8; it++) {
        int idx = it*256 + tid;
        if (idx < 1920) {
            int type = idx / 640;
            int rem  = idx % 640;
            int hblk = rem / 320;
            int wi   = rem % 320;
            long long mb = hblk ? m0b : m0a;
            long long goff = (type == 0 ? PI_OFF : type == 1 ? SG_OFF : MU_OFF) + mb*10;
            *((float4*)(out + goff) + wi) = obv[idx];
        }
    }
}

extern "C" void kernel_launch(void* const* d_in, const int* in_sizes, int n_in,
                              void* d_out, int out_size) {
    const float* pos_l    = (const float*)d_in[0];
    const float* pos_p    = (const float*)d_in[1];
    const float* Interact = (const float*)d_in[2];
    const int*   mask     = (const int*)d_in[3];
    const float* W_pi     = (const float*)d_in[4];
    const float* b_pi     = (const float*)d_in[5];
    const float* W_sigma  = (const float*)d_in[6];
    const float* b_sigma  = (const float*)d_in[7];
    const float* W_mu     = (const float*)d_in[8];
    const float* b_mu     = (const float*)d_in[9];
    float* out = (float*)d_out;

    pack_wf<<<16, 256>>>(W_pi, b_pi, W_sigma, b_sigma, W_mu, b_mu);

    cudaFuncSetAttribute(fused_kernel, cudaFuncAttributeMaxDynamicSharedMemorySize,
                         SMEM_BYTES);
    fused_kernel<<<BB * (NL/2) * 4, 256, SMEM_BYTES>>>(pos_l, pos_p, Interact,
                                                       mask, out);
}

// round 16
// speedup vs baseline: 1.0858x; 1.0823x over previous
#include <cuda_runtime.h>
#include <cuda_bf16.h>
#include <cstdint>

#define BB 16
#define NL 64
#define NP 512

// Output layout in d_out (float32, reference return order)
#define PI_OFF   0LL
#define SG_OFF   5242880LL          // M*10
#define MU_OFF   10485760LL
#define D_OFF    15728640LL
#define MK_OFF   16252928LL

// Pre-packed weight fragments (lane-major) + bias, built once per launch
__device__ __align__(16) unsigned g_wf[8 * 16 * 32];  // [ks][which][lane]
__device__ __align__(16) float    g_bs[32];

// smem (u32 offsets): atoms 4608 u32 (18432B, 64 j), wf 4096, bias 32
// Epilogue staging ob[3][128][10] = 3840 f32 aliases atoms (4608 u32).
#define AT_U     0
#define WF_U     4608
#define BS_U     8704
#define OB_U     0
#define SMEM_U   8736
#define SMEM_BYTES (SMEM_U*4)       // 34944 B -> 3 CTAs/SM (regs-limited)

// m16n8k16 bf16 MMA, fp32 accumulate
#define MMA(D, A, B0, B1) \
  asm volatile("mma.sync.aligned.m16n8k16.row.col.f32.bf16.bf16.f32 " \
      "{%0,%1,%2,%3}, {%4,%5,%6,%7}, {%8,%9}, {%0,%1,%2,%3};" \
      : "+f"((D)[0]), "+f"((D)[1]), "+f"((D)[2]), "+f"((D)[3]) \
      : "r"((A)[0]), "r"((A)[1]), "r"((A)[2]), "r"((A)[3]), "r"(B0), "r"(B1))

__device__ __forceinline__ void split4(float4 v, uint2& hv, uint2& lv) {
    __nv_bfloat162 h0 = __floats2bfloat162_rn(v.x, v.y);
    __nv_bfloat162 h1 = __floats2bfloat162_rn(v.z, v.w);
    float2 f0 = __bfloat1622float2(h0);
    float2 f1 = __bfloat1622float2(h1);
    __nv_bfloat162 l0 = __floats2bfloat162_rn(v.x - f0.x, v.y - f0.y);
    __nv_bfloat162 l1 = __floats2bfloat162_rn(v.z - f1.x, v.w - f1.y);
    hv = make_uint2(*(unsigned*)&h0, *(unsigned*)&h1);
    lv = make_uint2(*(unsigned*)&l0, *(unsigned*)&l1);
}

__device__ __forceinline__ void cp_async16(void* dst_smem, const void* src) {
    unsigned d = (unsigned)__cvta_generic_to_shared(dst_smem);
    asm volatile("cp.async.cg.shared.global [%0], [%1], 16;\n" :: "r"(d), "l"(src));
}
#define CP_COMMIT() asm volatile("cp.async.commit_group;\n")
#define CP_WAIT0()  asm volatile("cp.async.wait_group 0;\n")

// ---------------------------------------------------------------------------
// One-shot W fragment pack (identical to round 13)
// ---------------------------------------------------------------------------
__global__ void pack_wf(const float* __restrict__ Wpi, const float* __restrict__ bpi,
                        const float* __restrict__ Wsig, const float* __restrict__ bsig,
                        const float* __restrict__ Wmu, const float* __restrict__ bmu)
{
    int idx = blockIdx.x * 256 + threadIdx.x;    // 0..4095
    int ksw  = idx >> 9;
    int which = (idx >> 5) & 15;
    int ln   = idx & 31;
    int n    = which & 3, type = which >> 2;
    int qd_  = ln & 3,  g4_ = ln >> 2;
    int col  = 8*n + g4_;
    int kp   = 8*ksw + 2*qd_ + (type & 1);       // k rows 2kp, 2kp+1
    float w0 = 0.f, w1 = 0.f;
    if (col < 10)      { w0 = Wpi [kp*20 + col];      w1 = Wpi [kp*20 + 10 + col]; }
    else if (col < 20) { w0 = Wsig[kp*20 + col - 10]; w1 = Wsig[kp*20 + col]; }
    else if (col < 30) { w0 = Wmu [kp*20 + col - 20]; w1 = Wmu [kp*20 + col - 10]; }
    __nv_bfloat162 hh = __floats2bfloat162_rn(w0, w1);
    if (type >= 2) {
        float2 hf = __bfloat1622float2(hh);
        hh = __floats2bfloat162_rn(w0 - hf.x, w1 - hf.y);
    }
    g_wf[idx] = *(unsigned*)&hh;
    if (idx < 32) {
        float bv = 0.f;
        if (idx < 10) bv = bpi[idx];
        else if (idx < 20) bv = bsig[idx - 10];
        else if (idx < 30) bv = bmu[idx - 20];
        g_bs[idx] = bv;
    }
}

__global__ __launch_bounds__(256, 3)
void fused_kernel(const float* __restrict__ pos_l, const float* __restrict__ pos_p,
                  const float* __restrict__ X, const int* __restrict__ mask,
                  float* __restrict__ out)
{
    extern __shared__ unsigned smU[];
    float4*   sm4 = (float4*)(smU + AT_U);       // atom staging (64 j)
    unsigned* wf  = smU + WF_U;
    float*    bs  = (float*)(smU + BS_U);
    float*    ob  = (float*)(smU + OB_U);        // aliases atoms (post-GEMM)

    const int tid  = threadIdx.x;
    const int lane = tid & 31, w = tid >> 5;
    const int qd   = lane & 3, g4 = lane >> 2;
    const int blk  = blockIdx.x;                 // 4096: b(4b)|i2(5b)|jq(3b)
    const int b    = blk >> 8;
    const int i0   = 2 * ((blk >> 3) & 31);
    const int jofs = (blk & 7) * 64;
    const long long m0a = ((long long)(b*NL + i0))*NP + jofs;   // i0 rows
    const long long m0b = m0a + NP;                              // i0+1 rows
    const float4* Xg4 = (const float4*)X;

    // ---- stage atoms (64 j x 18 float4) + W fragments + bias ----
    {
        const float4* ag4 = (const float4*)(pos_p + ((long long)b*NP + jofs)*72);
        for (int u = tid; u < 1152; u += 256)
            cp_async16(sm4 + u, ag4 + u);
        #pragma unroll
        for (int u = 0; u < 4; u++)
            cp_async16((float4*)wf + u*256 + tid, (const float4*)g_wf + u*256 + tid);
        if (tid < 8)
            cp_async16((float4*)bs + tid, (const float4*)g_bs + tid);
        CP_COMMIT();
    }

    // warp row base: warps 0-3 -> i0 rows (64), warps 4-7 -> i0+1 rows
    const long long mw = (w < 4) ? (m0a + 16*w) : (m0b + 16*(w - 4));
    const float4* Xr = Xg4 + (mw + g4)*32 + qd;

    // ---- GEMM chunk 0 into registers (in flight during dist) ----
    float4 buf[2][4];
    #define LOADP(pp, B) { \
        _Pragma("unroll") \
        for (int u2 = 0; u2 < 4; u2++) { \
            int s2_ = u2 >> 1, r_ = u2 & 1; \
            (B)[u2] = Xr[(8*r_)*32 + 4*(2*(pp) + s2_)]; \
        } }
    LOADP(0, buf[0]);

    // ---- one barrier: atoms + wf + bs staged and visible ----
    CP_WAIT0();
    __syncthreads();

    // ---- min-distance: 4 threads per j = (half, which-i), 12 atoms each ----
    {
        const float* p0 = pos_l + (long long)(b*NL + i0)*3;
        const int jloc = tid >> 2;
        const int half = tid & 1, iw = (tid >> 1) & 1;
        float qx = iw ? p0[3] : p0[0];
        float qy = iw ? p0[4] : p0[1];
        float qz = iw ? p0[5] : p0[2];
        float qw = qx*qx + qy*qy + qz*qz;
        const float4* As = sm4 + jloc*18 + half*9;
        float m2 = 1e30f;
        #pragma unroll
        for (int u = 0; u < 3; u++) {            // 3 x (3 float4 = 4 atoms)
            float4 v0 = As[u*3], v1 = As[u*3+1], v2 = As[u*3+2];
            float c[12] = {v0.x,v0.y,v0.z,v0.w, v1.x,v1.y,v1.z,v1.w,
                           v2.x,v2.y,v2.z,v2.w};
            #pragma unroll
            for (int a = 0; a < 4; a++) {
                float ax = c[a*3], ay = c[a*3+1], az = c[a*3+2];
                float aw = ax*ax + ay*ay + az*az;
                float d2 = (qw + aw) - 2.f*(ax*qx + ay*qy + az*qz);
                d2 = (d2 < 0.f) ? 1e30f : d2;    // sqrt(neg)=NaN -> 10000
                m2 = fminf(m2, d2);
            }
        }
        m2 = fminf(m2, __shfl_xor_sync(0xffffffffu, m2, 1));  // combine halves
        if (half == 0) {
            float d = (m2 > 9e29f) ? 10000.f : sqrtf(m2);
            long long m = (iw ? m0b : m0a) + jloc;
            bool mk = (mask[m] != 0);
            out[D_OFF + m]  = mk ? d : 0.f;
            out[MK_OFF + m] = mk ? 1.f : 0.f;
        }
    }

    // ---- GEMM [128,128]x[128,32]: identical to round-13 champion ----
    float acc[4][4];
    #pragma unroll
    for (int n = 0; n < 4; n++) {
        float c0 = bs[8*n + 2*qd], c1 = bs[8*n + 2*qd + 1];
        acc[n][0] = c0; acc[n][1] = c1;
        acc[n][2] = c0; acc[n][3] = c1;
    }

    #pragma unroll
    for (int p = 0; p < 4; p++) {
        if (p < 3) LOADP(p + 1, buf[(p + 1) & 1]);
        #pragma unroll
        for (int s2 = 0; s2 < 2; s2++) {
            int ks = 2*p + s2;
            const unsigned* wfs = wf + ks*512 + lane;   // conflict-free LDS.32
            unsigned bw[16];
            #pragma unroll
            for (int q = 0; q < 16; q++) bw[q] = wfs[q*32];
            float4 x0 = buf[p & 1][s2*2];
            float4 x1 = buf[p & 1][s2*2 + 1];
            uint2 h0, l0, h1, l1;
            split4(x0, h0, l0); split4(x1, h1, l1);
            unsigned ah[4] = {h0.x, h1.x, h0.y, h1.y};
            unsigned al[4] = {l0.x, l1.x, l0.y, l1.y};
            #pragma unroll
            for (int n = 0; n < 4; n++) {
                MMA(acc[n], ah, bw[n],     bw[4 + n]);    // hi*Whi
                MMA(acc[n], al, bw[n],     bw[4 + n]);    // lo*Whi
                MMA(acc[n], ah, bw[8 + n], bw[12 + n]);   // hi*Wlo
            }
        }
    }
    __syncthreads();           // dist smem reads done before ob aliases atoms

    // ---- epilogue in fragment layout, stage to smem [3][128][10] ----
    {
        int rbase = 16*w + g4;   // logical row 0..127 (0-63 i0, 64-127 i0+1)
        #pragma unroll
        for (int h = 0; h < 2; h++) {
            int r = rbase + 8*h;
            float v0[4], v1[4];
            #pragma unroll
            for (int n = 0; n < 4; n++) {
                v0[n] = acc[n][2*h];
                v1[n] = acc[n][2*h + 1];
            }
            // pi = softmax over cols 0..9 (quad reduce)
            float mx = fmaxf(v0[0], v1[0]);
            if (qd == 0) mx = fmaxf(mx, fmaxf(v0[1], v1[1]));
            mx = fmaxf(mx, __shfl_xor_sync(0xffffffffu, mx, 1));
            mx = fmaxf(mx, __shfl_xor_sync(0xffffffffu, mx, 2));
            float e0 = __expf(v0[0] - mx), e1 = __expf(v1[0] - mx);
            float e8 = 0.f, e9 = 0.f;
            float ssum = e0 + e1;
            if (qd == 0) { e8 = __expf(v0[1] - mx); e9 = __expf(v1[1] - mx); ssum += e8 + e9; }
            ssum += __shfl_xor_sync(0xffffffffu, ssum, 1);
            ssum += __shfl_xor_sync(0xffffffffu, ssum, 2);
            float inv = __fdividef(1.f, ssum);
            float* prow = ob + r*10;
            *(float2*)(prow + 2*qd) = make_float2(e0*inv, e1*inv);
            if (qd == 0) *(float2*)(prow + 8) = make_float2(e8*inv, e9*inv);
            // sigma cols 10..19
            float* srow = ob + 1280 + r*10;
            if (qd >= 1) {
                float a0 = v0[1], a1 = v1[1];
                float l0 = (a0 > 0.f) ? a0 : 0.01f*a0;
                float l1 = (a1 > 0.f) ? a1 : 0.01f*a1;
                *(float2*)(srow + 2*qd - 2) =
                    make_float2(fmaxf(l0 + 1.1f, 1e-6f), fmaxf(l1 + 1.1f, 1e-6f));
            }
            if (qd <= 1) {
                float a0 = v0[2], a1 = v1[2];
                float l0 = (a0 > 0.f) ? a0 : 0.01f*a0;
                float l1 = (a1 > 0.f) ? a1 : 0.01f*a1;
                *(float2*)(srow + 6 + 2*qd) =
                    make_float2(fmaxf(l0 + 1.1f, 1e-6f), fmaxf(l1 + 1.1f, 1e-6f));
            }
            // mu cols 20..29
            float* mrow = ob + 2560 + r*10;
            if (qd >= 2) {
                float a0 = v0[2], a1 = v1[2];
                float l0 = (a0 > 0.f) ? a0 : 0.01f*a0;
                float l1 = (a1 > 0.f) ? a1 : 0.01f*a1;
                *(float2*)(mrow + 2*qd - 4) = make_float2(l0 + 1.f, l1 + 1.f);
            }
            if (qd <= 2) {
                float a0 = v0[3], a1 = v1[3];
                float l0 = (a0 > 0.f) ? a0 : 0.01f*a0;
                float l1 = (a1 > 0.f) ? a1 : 0.01f*a1;
                *(float2*)(mrow + 4 + 2*qd) = make_float2(l0 + 1.f, l1 + 1.f);
            }
        }
    }
    __syncthreads();

    // ---- coalesced float4 store: 3 outputs x 2 i-blocks x 160 float4 ----
    const float4* obv = (const float4*)ob;
    #pragma unroll
    for (int it = 0; it < 4; it++) {
        int idx = it*256 + tid;
        if (idx < 960) {
            int type = idx / 320;
            int rem  = idx % 320;
            int hblk = rem / 160;
            int wi   = rem % 160;
            long long mb = hblk ? m0b : m0a;
            long long goff = (type == 0 ? PI_OFF : type == 1 ? SG_OFF : MU_OFF) + mb*10;
            *((float4*)(out + goff) + wi) = obv[idx];
        }
    }
}

extern "C" void kernel_launch(void* const* d_in, const int* in_sizes, int n_in,
                              void* d_out, int out_size) {
    const float* pos_l    = (const float*)d_in[0];
    const float* pos_p    = (const float*)d_in[1];
    const float* Interact = (const float*)d_in[2];
    const int*   mask     = (const int*)d_in[3];
    const float* W_pi     = (const float*)d_in[4];
    const float* b_pi     = (const float*)d_in[5];
    const float* W_sigma  = (const float*)d_in[6];
    const float* b_sigma  = (const float*)d_in[7];
    const float* W_mu     = (const float*)d_in[8];
    const float* b_mu     = (const float*)d_in[9];
    float* out = (float*)d_out;

    pack_wf<<<16, 256>>>(W_pi, b_pi, W_sigma, b_sigma, W_mu, b_mu);

    cudaFuncSetAttribute(fused_kernel, cudaFuncAttributeMaxDynamicSharedMemorySize,
                         SMEM_BYTES);
    fused_kernel<<<BB * (NL/2) * 8, 256, SMEM_BYTES>>>(pos_l, pos_p, Interact,
                                                       mask, out);
}